// round 1
// baseline (speedup 1.0000x reference)
#include <cuda_runtime.h>
#include <cuda_bf16.h>
#include <math.h>

// ViT_15358803051012 — fully fused, one kernel.
// Block = 256 threads = 16 samples x 16 threads (thread t = output dim d).
// Warp = 2 samples (lanes 0-15 sample A, lanes 16-31 sample B).
//
// SMEM plan (floats):
//   PB  : [16][49*16] patches, later reused as tok2
//   V1  : [16][49*16] V1, later reused as tok3 (stride 8 within)
//   V2  : [16][49*8]
//   H   : [16][16] fc1 activations
//   LG  : [16][16] logits
//   PE  : [49*16] pos_emb
//   F1W : [16][396] fc1_w padded
//   F2W/F1B/F2B : small
//   WCH : per-7-patch weight chunk (layer1: 3*16 rows x 36 pad; layer2 reuses)

#define GRP 16        // samples per block
#define NTHR 256

// ---- smem layout (float offsets) ----
static constexpr int SM_PB  = 0;
static constexpr int SM_V1  = SM_PB  + GRP * 784;
static constexpr int SM_V2  = SM_V1  + GRP * 784;
static constexpr int SM_H   = SM_V2  + GRP * 392;
static constexpr int SM_LG  = SM_H   + GRP * 16;
static constexpr int SM_PE  = SM_LG  + GRP * 16;
static constexpr int SM_F1W = SM_PE  + 784;
static constexpr int SM_F2W = SM_F1W + 16 * 396;
static constexpr int SM_F1B = SM_F2W + 160;
static constexpr int SM_F2B = SM_F1B + 16;
static constexpr int SM_WCH = SM_F2B + 16;
static constexpr int WCH_SZ = 7 * 3 * 16 * 36;   // 12096 (layer1 chunk; layer2 fits inside)
static constexpr int SM_TOT = SM_WCH + WCH_SZ;   // 51280 floats = 205120 B

__device__ __forceinline__ float dot32_v4(const float* __restrict__ w, const float* tk) {
    float acc = 0.f;
#pragma unroll
    for (int i = 0; i < 8; i++) {
        float4 ww = *reinterpret_cast<const float4*>(w + 4 * i);
        acc = fmaf(tk[4 * i + 0], ww.x, acc);
        acc = fmaf(tk[4 * i + 1], ww.y, acc);
        acc = fmaf(tk[4 * i + 2], ww.z, acc);
        acc = fmaf(tk[4 * i + 3], ww.w, acc);
    }
    return acc;
}

__device__ __forceinline__ float dot16_v4(const float* __restrict__ w, const float* tk) {
    float acc = 0.f;
#pragma unroll
    for (int i = 0; i < 4; i++) {
        float4 ww = *reinterpret_cast<const float4*>(w + 4 * i);
        acc = fmaf(tk[4 * i + 0], ww.x, acc);
        acc = fmaf(tk[4 * i + 1], ww.y, acc);
        acc = fmaf(tk[4 * i + 2], ww.z, acc);
        acc = fmaf(tk[4 * i + 3], ww.w, acc);
    }
    return acc;
}

__global__ __launch_bounds__(NTHR, 1)
void vit_fused_kernel(
    const float* __restrict__ x,        // (B,3,28,28)
    const float* __restrict__ pos_emb,  // (7,7,16)
    const float* __restrict__ WQ1,      // (49,16,32)
    const float* __restrict__ WK1,
    const float* __restrict__ WV1,
    const float* __restrict__ WQ2,      // (49,8,16)
    const float* __restrict__ WK2,
    const float* __restrict__ WV2,
    const float* __restrict__ fc1w,     // (16,392)
    const float* __restrict__ fc1b,     // (16)
    const float* __restrict__ fc2w,     // (10,16)
    const float* __restrict__ fc2b,     // (10)
    float* __restrict__ out,            // (B,10)
    int B)
{
    extern __shared__ float sh[];

    const int tid  = threadIdx.x;
    const int lane = tid & 31;
    const int t    = tid & 15;       // dim index within sample
    const int ls   = tid >> 4;       // sample index within block
    const int shbase = lane & 16;    // lane base of my sample within the warp
    const int b0   = blockIdx.x * GRP;
    const int b    = b0 + ls;

    // ================= Phase 0: load x -> grayscale patches; stage constants =================
    for (int idx = tid; idx < GRP * 784; idx += NTHR) {
        int lsi = idx / 784;
        int pix = idx - lsi * 784;
        int bb = b0 + lsi;
        if (bb < B) {
            const float* xp = x + (size_t)bb * 2352 + pix;
            float g = 0.299f * xp[0] + 0.587f * xp[784] + 0.114f * xp[1568];
            int y  = pix / 28;
            int xx = pix - y * 28;
            int s  = (y >> 2) * 7 + (xx >> 2);
            int q  = (y & 3) * 4 + (xx & 3);
            sh[SM_PB + lsi * 784 + s * 16 + q] = g;
        }
    }
    for (int idx = tid; idx < 784; idx += NTHR) sh[SM_PE + idx] = pos_emb[idx];
    for (int idx = tid; idx < 6272; idx += NTHR) {
        int j = idx / 392, k = idx - j * 392;
        sh[SM_F1W + j * 396 + k] = fc1w[idx];
    }
    if (tid < 160) sh[SM_F2W + tid] = fc2w[tid];
    if (tid < 16)  sh[SM_F1B + tid] = fc1b[tid];
    if (tid < 10)  sh[SM_F2B + tid] = fc2b[tid];
    // (barrier provided by first chunk-load __syncthreads below)

    // ================= Layer 1: projections + attention gram =================
    float S1[16];
#pragma unroll
    for (int e = 0; e < 16; e++) S1[e] = 0.f;

    for (int c0 = 0; c0 < 49; c0 += 7) {
        __syncthreads();
        // stage 7 patches of WQ1/WK1/WV1 (rows padded to 36 floats)
#pragma unroll
        for (int m = 0; m < 3; m++) {
            const float* src = (m == 0) ? WQ1 : ((m == 1) ? WK1 : WV1);
            for (int idx = tid; idx < 7 * 512; idx += NTHR) {
                int j = idx >> 9, rr = idx & 511;
                int d = rr >> 5, i = rr & 31;
                sh[SM_WCH + ((j * 3 + m) * 16 + d) * 36 + i] = src[c0 * 512 + idx];
            }
        }
        __syncthreads();

        for (int s = c0; s < c0 + 7; s++) {
            // tok1[s] -> registers (broadcast smem reads)
            float tk[32];
            const float* pb = &sh[SM_PB + ls * 784 + s * 16];
            const float* pe = &sh[SM_PE + s * 16];
#pragma unroll
            for (int i = 0; i < 4; i++) {
                float4 a = *reinterpret_cast<const float4*>(pb + 4 * i);
                tk[4 * i + 0] = a.x; tk[4 * i + 1] = a.y; tk[4 * i + 2] = a.z; tk[4 * i + 3] = a.w;
                float4 p = *reinterpret_cast<const float4*>(pe + 4 * i);
                tk[16 + 4 * i + 0] = p.x; tk[16 + 4 * i + 1] = p.y;
                tk[16 + 4 * i + 2] = p.z; tk[16 + 4 * i + 3] = p.w;
            }
            const float* wq = &sh[SM_WCH + (((s - c0) * 3 + 0) * 16 + t) * 36];
            const float* wk = &sh[SM_WCH + (((s - c0) * 3 + 1) * 16 + t) * 36];
            const float* wv = &sh[SM_WCH + (((s - c0) * 3 + 2) * 16 + t) * 36];
            float q = dot32_v4(wq, tk) * 0.14285714285714285f;  // fold 1/sqrt(49)
            float k = dot32_v4(wk, tk);
            float v = dot32_v4(wv, tk);
            sh[SM_V1 + ls * 784 + s * 16 + t] = v;
            // S1[d][e] += q[d] * k[e]  via warp shuffle broadcast of k
#pragma unroll
            for (int e = 0; e < 16; e++) {
                float ke = __shfl_sync(0xffffffffu, k, shbase + e, 32);
                S1[e] = fmaf(q, ke, S1[e]);
            }
        }
    }
    __syncwarp();

    // A1[s,d] = sum_e S1[d,e] * V1[s,e]  -> write tok2 into PB
    for (int s = 0; s < 49; s++) {
        const float* vv = &sh[SM_V1 + ls * 784 + s * 16];
        float a = 0.f;
#pragma unroll
        for (int j = 0; j < 4; j++) {
            float4 v4 = *reinterpret_cast<const float4*>(vv + 4 * j);
            a = fmaf(S1[4 * j + 0], v4.x, a);
            a = fmaf(S1[4 * j + 1], v4.y, a);
            a = fmaf(S1[4 * j + 2], v4.z, a);
            a = fmaf(S1[4 * j + 3], v4.w, a);
        }
        sh[SM_PB + ls * 784 + s * 16 + t] = a;
    }
    __syncwarp();

    // softmax over d (16) per row s; rows distributed t, t+16, t+32, (t=0 also 48)
    for (int s = t; s < 49; s += 16) {
        float* row = &sh[SM_PB + ls * 784 + s * 16];
        float m = row[0];
#pragma unroll
        for (int e = 1; e < 16; e++) m = fmaxf(m, row[e]);
        float ex[16], sum = 0.f;
#pragma unroll
        for (int e = 0; e < 16; e++) { ex[e] = __expf(row[e] - m); sum += ex[e]; }
        float inv = 1.f / sum;
#pragma unroll
        for (int e = 0; e < 16; e++) row[e] = ex[e] * inv;
    }
    __syncwarp();

    // ================= Layer 2 =================
    float S2[8];
#pragma unroll
    for (int e = 0; e < 8; e++) S2[e] = 0.f;

    for (int c0 = 0; c0 < 49; c0 += 7) {
        __syncthreads();
#pragma unroll
        for (int m = 0; m < 3; m++) {
            const float* src = (m == 0) ? WQ2 : ((m == 1) ? WK2 : WV2);
            for (int idx = tid; idx < 7 * 128; idx += NTHR) {
                int j = idx >> 7, rr = idx & 127;
                int d = rr >> 4, i = rr & 15;
                sh[SM_WCH + ((j * 3 + m) * 8 + d) * 20 + i] = src[c0 * 128 + idx];
            }
        }
        __syncthreads();

        for (int s = c0; s < c0 + 7; s++) {
            float u[16];
            const float* pb = &sh[SM_PB + ls * 784 + s * 16];
#pragma unroll
            for (int i = 0; i < 4; i++) {
                float4 a = *reinterpret_cast<const float4*>(pb + 4 * i);
                u[4 * i + 0] = a.x; u[4 * i + 1] = a.y; u[4 * i + 2] = a.z; u[4 * i + 3] = a.w;
            }
            float q2 = 0.f, k2 = 0.f;
            if (t < 8) {
                const float* wq = &sh[SM_WCH + (((s - c0) * 3 + 0) * 8 + t) * 20];
                const float* wv = &sh[SM_WCH + (((s - c0) * 3 + 2) * 8 + t) * 20];
                q2 = dot16_v4(wq, u) * 0.14285714285714285f;
                float v2 = dot16_v4(wv, u);
                sh[SM_V2 + ls * 392 + s * 8 + t] = v2;
            } else {
                const float* wk = &sh[SM_WCH + (((s - c0) * 3 + 1) * 8 + (t - 8)) * 20];
                k2 = dot16_v4(wk, u);
            }
#pragma unroll
            for (int e = 0; e < 8; e++) {
                float ke = __shfl_sync(0xffffffffu, k2, shbase + 8 + e, 32);
                S2[e] = fmaf(q2, ke, S2[e]);   // q2==0 for t>=8, harmless
            }
        }
    }
    __syncwarp();

    // A2 -> tok3 (stored in V1 region, stride 8)
    if (t < 8) {
        for (int s = 0; s < 49; s++) {
            const float* vv = &sh[SM_V2 + ls * 392 + s * 8];
            float a = 0.f;
#pragma unroll
            for (int j = 0; j < 2; j++) {
                float4 v4 = *reinterpret_cast<const float4*>(vv + 4 * j);
                a = fmaf(S2[4 * j + 0], v4.x, a);
                a = fmaf(S2[4 * j + 1], v4.y, a);
                a = fmaf(S2[4 * j + 2], v4.z, a);
                a = fmaf(S2[4 * j + 3], v4.w, a);
            }
            sh[SM_V1 + ls * 392 + s * 8 + t] = a;
        }
    }
    __syncwarp();

    for (int s = t; s < 49; s += 16) {
        float* row = &sh[SM_V1 + ls * 392 + s * 8];
        float m = row[0];
#pragma unroll
        for (int e = 1; e < 8; e++) m = fmaxf(m, row[e]);
        float ex[8], sum = 0.f;
#pragma unroll
        for (int e = 0; e < 8; e++) { ex[e] = __expf(row[e] - m); sum += ex[e]; }
        float inv = 1.f / sum;
#pragma unroll
        for (int e = 0; e < 8; e++) row[e] = ex[e] * inv;
    }
    __syncwarp();

    // ================= FC head =================
    {
        float acc = sh[SM_F1B + t];
        const float* fr = &sh[SM_F1W + t * 396];
        const float* t3 = &sh[SM_V1 + ls * 392];
#pragma unroll 7
        for (int kk = 0; kk < 392; kk += 8) {
            float4 a0 = *reinterpret_cast<const float4*>(t3 + kk);
            float4 a1 = *reinterpret_cast<const float4*>(t3 + kk + 4);
            float4 w0 = *reinterpret_cast<const float4*>(fr + kk);
            float4 w1 = *reinterpret_cast<const float4*>(fr + kk + 4);
            acc = fmaf(a0.x, w0.x, acc); acc = fmaf(a0.y, w0.y, acc);
            acc = fmaf(a0.z, w0.z, acc); acc = fmaf(a0.w, w0.w, acc);
            acc = fmaf(a1.x, w1.x, acc); acc = fmaf(a1.y, w1.y, acc);
            acc = fmaf(a1.z, w1.z, acc); acc = fmaf(a1.w, w1.w, acc);
        }
        sh[SM_H + ls * 16 + t] = fmaxf(acc, 0.f);
    }
    __syncwarp();

    {
        float lg = 0.f;
        if (t < 10) {
            const float* w  = &sh[SM_F2W + t * 16];
            const float* hh = &sh[SM_H + ls * 16];
#pragma unroll
            for (int j = 0; j < 16; j++) lg = fmaf(hh[j], w[j], lg);
            lg += sh[SM_F2B + t];
        }
        sh[SM_LG + ls * 16 + t] = lg;
    }
    __syncwarp();

    if (t == 0 && b < B) {
        const float* lrow = &sh[SM_LG + ls * 16];
        float m = lrow[0];
#pragma unroll
        for (int c = 1; c < 10; c++) m = fmaxf(m, lrow[c]);
        float ex[10], sum = 0.f;
#pragma unroll
        for (int c = 0; c < 10; c++) { ex[c] = __expf(lrow[c] - m); sum += ex[c]; }
        float inv = 1.f / sum;
        float* o = out + (size_t)b * 10;
#pragma unroll
        for (int c = 0; c < 10; c++) o[c] = ex[c] * inv;
    }
}

extern "C" void kernel_launch(void* const* d_in, const int* in_sizes, int n_in,
                              void* d_out, int out_size) {
    const float* x   = (const float*)d_in[0];
    const float* pe  = (const float*)d_in[1];
    const float* WQ1 = (const float*)d_in[2];
    const float* WK1 = (const float*)d_in[3];
    const float* WV1 = (const float*)d_in[4];
    const float* WQ2 = (const float*)d_in[5];
    const float* WK2 = (const float*)d_in[6];
    const float* WV2 = (const float*)d_in[7];
    const float* f1w = (const float*)d_in[8];
    const float* f1b = (const float*)d_in[9];
    const float* f2w = (const float*)d_in[10];
    const float* f2b = (const float*)d_in[11];
    float* out = (float*)d_out;

    int B = in_sizes[0] / (3 * 28 * 28);
    int grid = (B + GRP - 1) / GRP;
    size_t smem = (size_t)SM_TOT * sizeof(float);

    cudaFuncSetAttribute(vit_fused_kernel,
                         cudaFuncAttributeMaxDynamicSharedMemorySize, (int)smem);
    vit_fused_kernel<<<grid, NTHR, smem>>>(x, pe, WQ1, WK1, WV1, WQ2, WK2, WV2,
                                           f1w, f1b, f2w, f2b, out, B);
}